// round 7
// baseline (speedup 1.0000x reference)
#include <cuda_runtime.h>
#include <cstdint>

#define BT       524288
#define ROWS     64
#define NTHREADS 512
#define NBLOCKS  (BT / ROWS)
#define SS       36

// ---------------- shared layout (float offsets) ----------------
#define FS_MEAN 0
#define FS_INV  64
#define FS_B1   128
#define FS_B2   256
#define FS_SRCW 288
#define FS_DSTW 352
#define FS_SRCB 416
#define FS_DSTB 432
#define FS_ENCW 448
#define FS_ENCB 704
#define FS_DECW 736      // transposed [2][96]
#define FS_DECB 928
#define F_XS   1024      // x blocked: [16 kc][65 float4]         4160 floats
#define F_W1   5184      // [64 k][128] linear                    8192
#define F_H2S  5184      // overlay after MLP1: [64][36]          2304
#define F_ATS  7488      //                      [64][36]         2304
#define F_H1   13376     // [64][132]                             8448
#define F_HS   21824     // [64][36]                              2304
#define F_W2   24128     // [128][32] linear                      4096
#define SMEM_FLOATS 28224
#define SMEM_BYTES  (SMEM_FLOATS * 4)   // 112896 B -> 2 CTAs/SM

typedef unsigned long long u64;

__device__ __forceinline__ u64 pack2(float x, float y) {
    u64 r; asm("mov.b64 %0,{%1,%2};" : "=l"(r) : "f"(x), "f"(y)); return r;
}
__device__ __forceinline__ u64 ffma2(u64 a, u64 b, u64 c) {
    u64 d; asm("fma.rn.f32x2 %0,%1,%2,%3;" : "=l"(d) : "l"(a), "l"(b), "l"(c)); return d;
}
__device__ __forceinline__ float2 unpack2(u64 v) {
    float2 f; asm("mov.b64 {%0,%1},%2;" : "=f"(f.x), "=f"(f.y) : "l"(v)); return f;
}
// row bit-swap for x blocked layout: swap bits [1:0] with [3:2]
__device__ __forceinline__ int rswz(int row) {
    return (row & 48) | ((row & 3) << 2) | ((row >> 2) & 3);
}

__global__ __launch_bounds__(NTHREADS, 2)
void ggat_kernel(
    const float* __restrict__ x,
    const float* __restrict__ norm_mean,
    const float* __restrict__ norm_std,
    const float* __restrict__ w1g, const float* __restrict__ b1,
    const float* __restrict__ w2g, const float* __restrict__ b2,
    const float* __restrict__ enc_w, const float* __restrict__ enc_b,
    const float* __restrict__ src_w, const float* __restrict__ src_b,
    const float* __restrict__ dst_w, const float* __restrict__ dst_b,
    const float* __restrict__ dec_w, const float* __restrict__ dec_b,
    float* __restrict__ out)
{
    extern __shared__ __align__(16) float smf[];
    float* xs2 = smf + F_XS;
    float* w1s = smf + F_W1;
    float* h1s = smf + F_H1;
    float* w2s = smf + F_W2;
    float* hs  = smf + F_HS;
    float* ats = smf + F_ATS;
    float* h2s = smf + F_H2S;

    const int t    = threadIdx.x;
    const int warp = t >> 5;
    const int lane = t & 31;
    const int row0 = blockIdx.x * ROWS;

    // ---------------- Phase 0: staging ----------------
    {
        const float4* xg = (const float4*)(x + (size_t)row0 * 64);
        #pragma unroll
        for (int i = t; i < 1024; i += NTHREADS) {
            float4 v = __ldg(&xg[i]);
            int row = i >> 4, kc = i & 15;
            ((float4*)xs2)[kc * 65 + rswz(row)] = v;
        }
        const float4* w1g4 = (const float4*)w1g;
        #pragma unroll
        for (int i = t; i < 2048; i += NTHREADS) ((float4*)w1s)[i] = __ldg(&w1g4[i]);
        const float4* w2g4 = (const float4*)w2g;
        #pragma unroll
        for (int i = t; i < 1024; i += NTHREADS) ((float4*)w2s)[i] = __ldg(&w2g4[i]);
        if (t < 64) {
            smf[FS_MEAN + t] = norm_mean[t];
            smf[FS_INV + t]  = 1.0f / (norm_std[t] + 1e-8f);
            smf[FS_SRCW + t] = src_w[t];
            smf[FS_DSTW + t] = dst_w[t];
        }
        if (t < 128) smf[FS_B1 + t] = b1[t];
        if (t < 32)  { smf[FS_B2 + t] = b2[t]; smf[FS_ENCB + t] = enc_b[t]; }
        if (t < 16)  { smf[FS_SRCB + t] = src_b[t]; smf[FS_DSTB + t] = dst_b[t]; }
        if (t < 256) smf[FS_ENCW + t] = enc_w[t];
        if (t < 192) smf[FS_DECW + (t & 1) * 96 + (t >> 1)] = dec_w[t];
        if (t < 2)   smf[FS_DECB + t] = dec_b[t];
    }
    __syncthreads();

    if (warp < 8) {
        // ---------- Phase 1: MLP1. Warp tile: 16 rows x 64 cols ----------
        const int cg   = warp & 1;          // col half
        const int rg4  = warp >> 1;         // row group (16 rows)
        const int q    = lane >> 3;         // 0..3
        const int tc   = lane & 7;          // 0..7
        const int rowbase = rg4 * 16;
        const int chunkA  = cg * 16 + tc;       // float4 col chunk
        const int chunkB  = cg * 16 + 8 + tc;

        u64 acc[4][4];
        #pragma unroll
        for (int i = 0; i < 4; i++)
            #pragma unroll
            for (int j = 0; j < 4; j++) acc[i][j] = 0ull;

        #pragma unroll 2
        for (int kc = 0; kc < 16; kc++) {
            float4 x4[4];
            #pragma unroll
            for (int i = 0; i < 4; i++)
                x4[i] = ((const float4*)xs2)[kc * 65 + rowbase + (i << 2) + q];
            // x4[i] holds row rowbase+4q+i, k = 4kc..4kc+3
            #pragma unroll
            for (int j = 0; j < 4; j++) {
                const int k = kc * 4 + j;
                ulonglong2 wA = *(const ulonglong2*)&w1s[k * 128 + chunkA * 4];
                ulonglong2 wB = *(const ulonglong2*)&w1s[k * 128 + chunkB * 4];
                #pragma unroll
                for (int i = 0; i < 4; i++) {
                    float a = ((const float*)&x4[i])[j];
                    u64 ap = pack2(a, a);
                    acc[i][0] = ffma2(ap, wA.x, acc[i][0]);
                    acc[i][1] = ffma2(ap, wA.y, acc[i][1]);
                    acc[i][2] = ffma2(ap, wB.x, acc[i][2]);
                    acc[i][3] = ffma2(ap, wB.y, acc[i][3]);
                }
            }
        }
        float4 bA = *(const float4*)&smf[FS_B1 + chunkA * 4];
        float4 bB = *(const float4*)&smf[FS_B1 + chunkB * 4];
        #pragma unroll
        for (int i = 0; i < 4; i++) {
            const int row = rowbase + 4 * q + i;
            float2 u0 = unpack2(acc[i][0]);
            float2 u1 = unpack2(acc[i][1]);
            float2 u2 = unpack2(acc[i][2]);
            float2 u3 = unpack2(acc[i][3]);
            *(float4*)&h1s[row * 132 + chunkA * 4] =
                make_float4(fmaxf(u0.x + bA.x, 0.f), fmaxf(u0.y + bA.y, 0.f),
                            fmaxf(u1.x + bA.z, 0.f), fmaxf(u1.y + bA.w, 0.f));
            *(float4*)&h1s[row * 132 + chunkB * 4] =
                make_float4(fmaxf(u2.x + bB.x, 0.f), fmaxf(u2.y + bB.y, 0.f),
                            fmaxf(u3.x + bB.z, 0.f), fmaxf(u3.y + bB.w, 0.f));
        }
    } else {
        // ---------- Phase 1b: group encoder on warps 8-15 ----------
        #pragma unroll
        for (int it = 0; it < 2; it++) {
            const int task = (t - 256) + it * 256;
            const int row  = task >> 3;
            const int g    = task & 7;
            const int base = g * 8;
            const float4* xr = (const float4*)(x + (size_t)(row0 + row) * 64 + base);
            float4 xa = __ldg(xr), xb = __ldg(xr + 1);
            float xv[8] = {xa.x, xa.y, xa.z, xa.w, xb.x, xb.y, xb.z, xb.w};
            float xn[8];
            #pragma unroll
            for (int f = 0; f < 8; f++)
                xn[f] = (xv[f] - smf[FS_MEAN + base + f]) * smf[FS_INV + base + f];
            ulonglong2 eb = *(const ulonglong2*)&smf[FS_ENCB + g * 4];
            u64 e01 = eb.x, e23 = eb.y;
            #pragma unroll
            for (int f = 0; f < 8; f++) {
                ulonglong2 wf = *(const ulonglong2*)&smf[FS_ENCW + (base + f) * 4];
                u64 xp = pack2(xn[f], xn[f]);
                e01 = ffma2(xp, wf.x, e01);
                e23 = ffma2(xp, wf.y, e23);
            }
            float2 v01 = unpack2(e01), v23 = unpack2(e23);
            *(float4*)&hs[row * SS + g * 4] =
                make_float4(fmaxf(v01.x, 0.f), fmaxf(v01.y, 0.f),
                            fmaxf(v23.x, 0.f), fmaxf(v23.y, 0.f));
        }
    }
    __syncthreads();   // h1, hs ready; xs2/w1 dead

    if (warp < 4) {
        // ---------- Phase 2: MLP2 on warps 0-3, k chunked by 4 ----------
        const int rowg = t >> 3;        // 0..15
        const int c0   = (t & 7) * 4;
        u64 a01[4], a23[4];
        #pragma unroll
        for (int i = 0; i < 4; i++) { a01[i] = 0ull; a23[i] = 0ull; }

        #pragma unroll 2
        for (int kc = 0; kc < 32; kc++) {
            float4 hv[4];
            #pragma unroll
            for (int i = 0; i < 4; i++)
                hv[i] = *(const float4*)&h1s[(rowg + 16 * i) * 132 + kc * 4];
            #pragma unroll
            for (int j = 0; j < 4; j++) {
                ulonglong2 w = *(const ulonglong2*)&w2s[(kc * 4 + j) * 32 + c0];
                #pragma unroll
                for (int i = 0; i < 4; i++) {
                    float a = ((const float*)&hv[i])[j];
                    u64 ap = pack2(a, a);
                    a01[i] = ffma2(ap, w.x, a01[i]);
                    a23[i] = ffma2(ap, w.y, a23[i]);
                }
            }
        }
        float4 bb = *(const float4*)&smf[FS_B2 + c0];
        #pragma unroll
        for (int i = 0; i < 4; i++) {
            float2 u0 = unpack2(a01[i]), u1 = unpack2(a23[i]);
            *(float4*)&h2s[(rowg + 16 * i) * SS + c0] =
                make_float4(fmaxf(u0.x + bb.x, 0.f), fmaxf(u0.y + bb.y, 0.f),
                            fmaxf(u1.x + bb.z, 0.f), fmaxf(u1.y + bb.w, 0.f));
        }
    } else {
        // ---------- Phase 3: attention on warps 4-15 ----------
        const int w4 = warp - 4;            // 0..11
        const int r2 = lane >> 4, hd = (lane >> 3) & 1, g = lane & 7;
        #pragma unroll
        for (int p = 0; p < 3; p++) {
            const int row = (p * 12 + w4) * 2 + r2;
            if (row < ROWS) {
                float4 hg4 = *(const float4*)&hs[row * SS + g * 4];
                float hge[4] = {hg4.x, hg4.y, hg4.z, hg4.w};

                ulonglong2 sb0 = *(const ulonglong2*)&smf[FS_SRCB + hd * 8];
                ulonglong2 sb1 = *(const ulonglong2*)&smf[FS_SRCB + hd * 8 + 4];
                ulonglong2 db0 = *(const ulonglong2*)&smf[FS_DSTB + hd * 8];
                ulonglong2 db1 = *(const ulonglong2*)&smf[FS_DSTB + hd * 8 + 4];
                u64 sp[4] = {sb0.x, sb0.y, sb1.x, sb1.y};
                u64 dp[4] = {db0.x, db0.y, db1.x, db1.y};
                #pragma unroll
                for (int e = 0; e < 4; e++) {
                    u64 hp = pack2(hge[e], hge[e]);
                    ulonglong2 sv0 = *(const ulonglong2*)&smf[FS_SRCW + e * 16 + hd * 8];
                    ulonglong2 sv1 = *(const ulonglong2*)&smf[FS_SRCW + e * 16 + hd * 8 + 4];
                    ulonglong2 dv0 = *(const ulonglong2*)&smf[FS_DSTW + e * 16 + hd * 8];
                    ulonglong2 dv1 = *(const ulonglong2*)&smf[FS_DSTW + e * 16 + hd * 8 + 4];
                    sp[0] = ffma2(hp, sv0.x, sp[0]); sp[1] = ffma2(hp, sv0.y, sp[1]);
                    sp[2] = ffma2(hp, sv1.x, sp[2]); sp[3] = ffma2(hp, sv1.y, sp[3]);
                    dp[0] = ffma2(hp, dv0.x, dp[0]); dp[1] = ffma2(hp, dv0.y, dp[1]);
                    dp[2] = ffma2(hp, dv1.x, dp[2]); dp[3] = ffma2(hp, dv1.y, dp[3]);
                }
                float sr[8], ds[8];
                #pragma unroll
                for (int j = 0; j < 4; j++) {
                    float2 s = unpack2(sp[j]); sr[2*j] = s.x; sr[2*j+1] = s.y;
                    float2 d = unpack2(dp[j]); ds[2*j] = d.x; ds[2*j+1] = d.y;
                }
                float sc[8];
                #pragma unroll
                for (int k = 0; k < 8; k++) {
                    float s = 0.f;
                    const int srcl = (lane & 24) | k;
                    #pragma unroll
                    for (int a = 0; a < 8; a++)
                        s += sr[a] * __shfl_sync(0xffffffffu, ds[a], srcl);
                    sc[k] = s * 0.35355339059327373f;
                }
                float m = sc[0];
                #pragma unroll
                for (int k = 1; k < 8; k++) m = fmaxf(m, sc[k]);
                float sum = 0.f;
                #pragma unroll
                for (int k = 0; k < 8; k++) { sc[k] = __expf(sc[k] - m); sum += sc[k]; }
                const float invs = 1.f / sum;

                u64 a01 = 0ull, a23 = 0ull;
                #pragma unroll
                for (int k = 0; k < 8; k++) {
                    float pr = sc[k] * invs;
                    u64 pp = pack2(pr, pr);
                    ulonglong2 hv = *(const ulonglong2*)&hs[row * SS + k * 4];
                    a01 = ffma2(pp, hv.x, a01);
                    a23 = ffma2(pp, hv.y, a23);
                }
                float2 u0 = unpack2(a01), u1 = unpack2(a23);
                float av[4] = {u0.x, u0.y, u1.x, u1.y};
                #pragma unroll
                for (int e = 0; e < 4; e++)
                    av[e] += __shfl_xor_sync(0xffffffffu, av[e], 8);
                if (hd == 0)
                    *(float4*)&ats[row * SS + g * 4] = make_float4(av[0], av[1], av[2], av[3]);
            }
        }
    }
    __syncthreads();   // h2s, ats ready

    // ---------------- Phase 4: decoder ----------------
    if (t < ROWS * 2) {
        const int row = t >> 1;
        const int o   = t & 1;
        float acc = smf[FS_DECB + o];
        const float* wv = smf + FS_DECW + o * 96;
        const float* srcs[3] = {h2s, hs, ats};
        #pragma unroll
        for (int s = 0; s < 3; s++) {
            const float* sv = srcs[s] + row * SS;
            const int off = s * 32;
            #pragma unroll
            for (int j = 0; j < 8; j++) {
                float4 v  = *(const float4*)&sv[j * 4];
                float4 wa = *(const float4*)&wv[off + j * 4];
                acc += v.x * wa.x + v.y * wa.y + v.z * wa.z + v.w * wa.w;
            }
        }
        out[(size_t)(row0 + row) * 2 + o] = acc;
    }
}

extern "C" void kernel_launch(void* const* d_in, const int* in_sizes, int n_in,
                              void* d_out, int out_size)
{
    const float* x         = (const float*)d_in[0];
    const float* norm_mean = (const float*)d_in[1];
    const float* norm_std  = (const float*)d_in[2];
    const float* w1        = (const float*)d_in[3];
    const float* b1        = (const float*)d_in[4];
    const float* w2        = (const float*)d_in[5];
    const float* b2        = (const float*)d_in[6];
    const float* enc_w     = (const float*)d_in[7];
    const float* enc_b     = (const float*)d_in[8];
    const float* src_w     = (const float*)d_in[9];
    const float* src_b     = (const float*)d_in[10];
    const float* dst_w     = (const float*)d_in[11];
    const float* dst_b     = (const float*)d_in[12];
    const float* dec_w     = (const float*)d_in[13];
    const float* dec_b     = (const float*)d_in[14];
    float* out = (float*)d_out;

    cudaFuncSetAttribute(ggat_kernel,
                         cudaFuncAttributeMaxDynamicSharedMemorySize, SMEM_BYTES);
    ggat_kernel<<<NBLOCKS, NTHREADS, SMEM_BYTES>>>(
        x, norm_mean, norm_std, w1, b1, w2, b2,
        enc_w, enc_b, src_w, src_b, dst_w, dst_b, dec_w, dec_b, out);
}